// round 14
// baseline (speedup 1.0000x reference)
#include <cuda_runtime.h>
#include <cstdint>

// RSNALoss, two-kernel, deterministically load-balanced:
//  K1 (740 blocks x 128 thr): each block scans seq_lens -> prefix of chunk
//  counts (NC total 128-row chunks), takes the contiguous global chunk range
//  [k*NC/740, (k+1)*NC/740)  (+-1 chunk balance, pure function of seq_lens).
//  Static depth-3 cp.async pipeline (constant wait_group 2: every iteration
//  commits exactly one group, empty groups predicated off). Per chunk: consume
//  one row/thread from smem, block-reduce 20 accumulators, write slot
//  [acc][b][c]. Unwritten slots stay 0 (zero-init device array) -> K2 sums all.
//  K2 (128 blocks x 128 thr): block b sums batch b's 64 chunk slots (coalesced),
//  computes exam/image terms; atomic-ticket last block reduces 128 batch
//  contributions to the scalar. Ticket only selects the finalizer -> deterministic.

#define BATCH 128
#define SEQ   8192
#define NT    128
#define CHUNK 128
#define MAXC  64                 // max chunks per batch (8192/128)
#define G     740                // K1 grid (148 SMs x 5 resident)
#define NACC  20
#define F4PT  320                // float4 per tensor per chunk (1280 floats)

#define IMAGE_WEIGHT 0.0736196319f

__constant__ float c_w[9] = {
    0.0736196319f, 0.09202453988f, 0.1042944785f, 0.1042944785f,
    0.1877300613f, 0.06257668712f, 0.06257668712f, 0.2346625767f,
    0.0782208589f
};

// [acc][b][c]; zero-initialized; slots for c >= nct_b are never written -> stay 0.
__device__ float g_partials[NACC * BATCH * MAXC];
__device__ float g_bnum[BATCH], g_bws[BATCH];
__device__ unsigned int g_ticket2;   // zero-init; reset by K2 finalizer

__device__ __forceinline__ void cp16(uint32_t s, const void* g, bool p)
{
    asm volatile(
        "{ .reg .pred q; setp.ne.u32 q, %2, 0;"
        "  @q cp.async.cg.shared.global [%0], [%1], 16; }"
        :: "r"(s), "l"(g), "r"((int)p));
}

__global__ __launch_bounds__(NT, 5)
void rsna_chunks_kernel(const float* __restrict__ pred,
                        const float* __restrict__ label,
                        const int*   __restrict__ seq_lens)
{
    const int tid = threadIdx.x;

    __shared__ __align__(16) float s_pred[3][CHUNK * 10];
    __shared__ __align__(16) float s_lab [3][CHUNK * 10];
    __shared__ int   s_pfx[BATCH + 1];
    __shared__ int   s_sl [BATCH];
    __shared__ int   s_tmp[BATCH];
    __shared__ float s_red[4 * NACC];

    // ---- prefix scan of chunk counts (Hillis-Steele over 128) ----
    {
        const int sl = __ldg(&seq_lens[tid]);
        s_sl[tid]  = sl;
        s_tmp[tid] = (sl + CHUNK - 1) >> 7;
        __syncthreads();
#pragma unroll
        for (int off = 1; off < BATCH; off <<= 1) {
            const int v = (tid >= off) ? s_tmp[tid - off] : 0;
            __syncthreads();
            s_tmp[tid] += v;
            __syncthreads();
        }
        if (tid == 0) s_pfx[0] = 0;
        s_pfx[tid + 1] = s_tmp[tid];
        __syncthreads();
    }

    const int NC  = s_pfx[BATCH];                      // total valid chunks
    const int a0  = (blockIdx.x * NC) / G;
    const int cnt = ((blockIdx.x + 1) * NC) / G - a0;  // +-1 balanced

    // binary search: b with s_pfx[b] <= g < s_pfx[b+1]
    auto find_b = [&](int g) -> int {
        int lo = 0, hi = BATCH;
#pragma unroll
        for (int i = 0; i < 7; i++) {
            const int mid = (lo + hi) >> 1;
            if (s_pfx[mid] <= g) lo = mid; else hi = mid;
        }
        return lo;
    };

    auto prefetch = [&](int c) {
        const int  buf = c % 3;
        const bool on  = (c < cnt);
        const int  g   = on ? (a0 + c) : 0;
        const int  b   = find_b(g);
        const int  cl  = g - s_pfx[b];
        const int  lim = on ? (s_sl[b] - cl * CHUNK) * 10 : 0;
        const float4* pg = (const float4*)pred  + (size_t)b * (SEQ * 10 / 4) + cl * F4PT;
        const float4* lg = (const float4*)label + (size_t)b * (SEQ * 10 / 4) + cl * F4PT;
        const uint32_t sp = (uint32_t)__cvta_generic_to_shared(&s_pred[buf][0]);
        const uint32_t sy = (uint32_t)__cvta_generic_to_shared(&s_lab [buf][0]);
#pragma unroll
        for (int j = 0; j < 5; j++) {          // 640 float4 over 128 threads
            const int idx = tid + j * NT;
            if (idx < F4PT) {
                cp16(sp + idx * 16, pg + idx, (idx * 4) < lim);
            } else {
                const int i2 = idx - F4PT;
                cp16(sy + i2 * 16, lg + i2, (i2 * 4) < lim);
            }
        }
        asm volatile("cp.async.commit_group;");  // ALWAYS: keeps wait counts static
    };

    const int wid  = tid >> 5;
    const int lane = tid & 31;

    prefetch(0);
    prefetch(1);

    for (int c = 0; c < cnt; c++) {
        prefetch(c + 2);                         // (c+2)%3: not consumed, not in-wait
        asm volatile("cp.async.wait_group 2;");  // chunk c's group complete
        __syncthreads();

        const int g   = a0 + c;
        const int b   = find_b(g);
        const int cl  = g - s_pfx[b];
        const int buf = c % 3;

        float acc[NACC];
#pragma unroll
        for (int i = 0; i < NACC; i++) acc[i] = 0.0f;

        const int row = cl * CHUNK + tid;
        if (row < s_sl[b]) {
            const float2* pr = (const float2*)&s_pred[buf][tid * 10];
            const float2* lr = (const float2*)&s_lab [buf][tid * 10];
            float2 p0 = pr[0], p1 = pr[1], p2 = pr[2], p3 = pr[3], p4 = pr[4];
            float2 l0 = lr[0], l1 = lr[1], l2 = lr[2], l3 = lr[3], l4 = lr[4];

            acc[0] += p0.y; acc[1] += p1.x; acc[2] += p1.y; acc[3] += p2.x;
            acc[4] += p2.y; acc[5] += p3.x; acc[6] += p3.y; acc[7] += p4.x;
            acc[8] += p4.y;

            acc[9]  += l0.y; acc[10] += l1.x; acc[11] += l1.y; acc[12] += l2.x;
            acc[13] += l2.y; acc[14] += l3.x; acc[15] += l3.y; acc[16] += l4.x;
            acc[17] += l4.y;

            const float p0v = p0.x, y0v = l0.x;
            acc[18] += y0v;
            acc[19] += -(y0v * __logf(p0v) + (1.0f - y0v) * __logf(1.0f - p0v));
        }

        // block reduce 20 accs
#pragma unroll
        for (int i = 0; i < NACC; i++) {
#pragma unroll
            for (int off = 16; off > 0; off >>= 1)
                acc[i] += __shfl_xor_sync(0xFFFFFFFFu, acc[i], off);
        }
        if (lane == 0) {
#pragma unroll
            for (int i = 0; i < NACC; i++) s_red[wid * NACC + i] = acc[i];
        }
        __syncthreads();   // also protects s_pred[buf] before its reuse

        if (tid < NACC) {
            float s = s_red[tid] + s_red[NACC + tid] +
                      s_red[2 * NACC + tid] + s_red[3 * NACC + tid];
            g_partials[(tid * BATCH + b) * MAXC + cl] = s;
        }
    }

    asm volatile("cp.async.wait_group 0;");
}

__global__ __launch_bounds__(NT)
void rsna_final_kernel(const int* __restrict__ seq_lens,
                       float* __restrict__ out)
{
    const int b = blockIdx.x;
    const int t = threadIdx.x;

    __shared__ float s2[NACC * MAXC];    // [acc][c] for this batch
#pragma unroll
    for (int i = 0; i < 10; i++) {
        const int idx = t + i * NT;                 // 1280 values
        const int a = idx >> 6, c = idx & 63;
        s2[idx] = g_partials[(a * BATCH + b) * MAXC + c];   // coalesced runs
    }
    __syncthreads();

    __shared__ float s_a[NACC];
    if (t < NACC) {
        float s = 0.0f;
#pragma unroll
        for (int j = 0; j < MAXC; j++) s += s2[t * MAXC + j];
        s_a[t] = s;
    }
    __syncthreads();

    if (t == 0) {
        const float len = (float)__ldg(&seq_lens[b]);
        const float inv = 1.0f / len;
        float exam = 0.0f;
#pragma unroll
        for (int c = 0; c < 9; c++) {
            const float pm = s_a[c]     * inv;
            const float ym = s_a[9 + c] * inv;
            exam += c_w[c] * (-(ym * __logf(pm) + (1.0f - ym) * __logf(1.0f - pm)));
        }
        const float y0m = s_a[18] * inv;
        const float iw  = IMAGE_WEIGHT * y0m;
        g_bnum[b] = exam + s_a[19] * iw;
        g_bws[b]  = iw * len;
    }

    // ---- ticket: last block reduces the 128 batch contributions ----
    __shared__ int s_last;
    __threadfence();
    __syncthreads();
    if (t == 0) {
        const unsigned tk = atomicAdd(&g_ticket2, 1u);
        s_last = (tk == (unsigned)(BATCH - 1)) ? 1 : 0;
    }
    __syncthreads();
    if (!s_last) return;

    if (t == 0) g_ticket2 = 0;
    __threadfence();

    float num  = g_bnum[t];
    float wsum = g_bws[t];
#pragma unroll
    for (int off = 16; off > 0; off >>= 1) {
        num  += __shfl_xor_sync(0xFFFFFFFFu, num,  off);
        wsum += __shfl_xor_sync(0xFFFFFFFFu, wsum, off);
    }
    __shared__ float s_num[4], s_ws[4];
    const int wid = t >> 5, lane = t & 31;
    if (lane == 0) { s_num[wid] = num; s_ws[wid] = wsum; }
    __syncthreads();
    if (t == 0) {
        float n = 0.0f, w = 0.0f;
#pragma unroll
        for (int i = 0; i < 4; i++) { n += s_num[i]; w += s_ws[i]; }
        float sumw = 0.0f;
#pragma unroll
        for (int c = 0; c < 9; c++) sumw += c_w[c];
        out[0] = n / ((float)BATCH * sumw + w);
    }
}

extern "C" void kernel_launch(void* const* d_in, const int* in_sizes, int n_in,
                              void* d_out, int out_size)
{
    const float* pred  = (const float*)d_in[0];
    const float* label = (const float*)d_in[1];
    const int*   slens = (const int*)d_in[2];
    float* out = (float*)d_out;

    rsna_chunks_kernel<<<G, NT>>>(pred, label, slens);
    rsna_final_kernel<<<BATCH, NT>>>(slens, out);
}

// round 15
// speedup vs baseline: 1.6875x; 1.6875x over previous
#include <cuda_runtime.h>
#include <cstdint>

// RSNALoss fused, smem-staged, interleaved chunks, STATIC depth-3 pipeline:
//  1024 blocks (128 thr) = 8 slots/batch x 128 batches. Block (b,slot) processes
//  chunks slot, slot+8, slot+16, ... (128 rows each). 3 smem buffers; EVERY
//  iteration commits exactly one cp.async group (empty ones fully predicated
//  off), so wait_group 2 is a compile-time constant -> no register bloat
//  (the branchy depth-4 variant hit 96 regs and regressed).
//  Last block (atomic ticket) finalizes. Deterministic: ticket only selects the
//  finalizing block; the partial array it reads is complete and fixed.

#define BATCH 128
#define SEQ   8192
#define NT    128
#define CHUNK 128                       // rows per chunk (== NT)
#define CH10  (CHUNK * 10)              // 1280 floats per tensor per chunk
#define F4PT  (CH10 / 4)                // 320 float4 per tensor per chunk
#define SLOTS 8                         // blocks per batch
#define MAXCH 8                         // max chunks per block
#define DEPTH 3
#define NBLK  (BATCH * SLOTS)           // 1024 blocks
#define NACC  20
#define NWARP (NT / 32)

#define IMAGE_WEIGHT 0.0736196319f

__constant__ float c_w[9] = {
    0.0736196319f, 0.09202453988f, 0.1042944785f, 0.1042944785f,
    0.1877300613f, 0.06257668712f, 0.06257668712f, 0.2346625767f,
    0.0782208589f
};

__device__ __align__(16) float g_partials[NACC * NBLK];  // [acc][b*SLOTS + slot]
__device__ unsigned int g_ticket;                        // zero-init; reset by last block

__device__ __forceinline__ void cp16(uint32_t s, const void* g, bool p)
{
    asm volatile(
        "{ .reg .pred q; setp.ne.u32 q, %2, 0;"
        "  @q cp.async.cg.shared.global [%0], [%1], 16; }"
        :: "r"(s), "l"(g), "r"((int)p));
}

__global__ __launch_bounds__(NT, 7)
void rsna_fused_kernel(const float* __restrict__ pred,
                       const float* __restrict__ label,
                       const int*   __restrict__ seq_lens,
                       float* __restrict__ out)
{
    const int b    = blockIdx.y;
    const int slot = blockIdx.x;
    const int tid  = threadIdx.x;
    const int sl   = __ldg(&seq_lens[b]);

    __shared__ __align__(16) float s_pred[DEPTH][CH10];
    __shared__ __align__(16) float s_lab [DEPTH][CH10];

    float acc[NACC];
#pragma unroll
    for (int i = 0; i < NACC; i++) acc[i] = 0.0f;

    // chunks of batch b: 0..nct-1; this block takes slot, slot+SLOTS, ...
    const int nct = (sl + CHUNK - 1) / CHUNK;              // 1..64
    int nch = (nct - slot + SLOTS - 1) / SLOTS;
    nch = max(0, min(nch, MAXCH));

    const float* pbase = pred  + (size_t)b * SEQ * 10;
    const float* lbase = label + (size_t)b * SEQ * 10;

    // Always commits one group; loads predicated off when c >= nch or past sl.
    auto prefetch = [&](int c) {
        const int  buf = c % DEPTH;
        const bool on  = (c < nch);
        const int  cb  = (slot + c * SLOTS) * CHUNK;       // chunk base row
        const int  lim = on ? (sl - cb) * 10 : 0;          // valid floats in chunk
        const float4* pg = (const float4*)(pbase + (size_t)cb * 10);
        const float4* lg = (const float4*)(lbase + (size_t)cb * 10);
        const uint32_t sp = (uint32_t)__cvta_generic_to_shared(&s_pred[buf][0]);
        const uint32_t sy = (uint32_t)__cvta_generic_to_shared(&s_lab [buf][0]);
#pragma unroll
        for (int j = 0; j < 5; j++) {       // 640 float4 over 128 threads
            const int idx = tid + j * NT;
            if (idx < F4PT) {
                cp16(sp + idx * 16, pg + idx, (idx * 4) < lim);
            } else {
                const int i2 = idx - F4PT;
                cp16(sy + i2 * 16, lg + i2, (i2 * 4) < lim);
            }
        }
        asm volatile("cp.async.commit_group;");  // ALWAYS -> static wait counts
    };

    prefetch(0);
    prefetch(1);

    for (int c = 0; c < nch; c++) {
        prefetch(c + 2);                         // writes (c+2)%3: free this iter
        asm volatile("cp.async.wait_group 2;");  // chunk c's group complete
        __syncthreads();

        const int buf = c % DEPTH;
        const int row = (slot + c * SLOTS) * CHUNK + tid;
        if (row < sl) {
            const float2* pr = (const float2*)&s_pred[buf][tid * 10];
            const float2* lr = (const float2*)&s_lab [buf][tid * 10];
            float2 p0 = pr[0], p1 = pr[1], p2 = pr[2], p3 = pr[3], p4 = pr[4];
            float2 l0 = lr[0], l1 = lr[1], l2 = lr[2], l3 = lr[3], l4 = lr[4];

            acc[0] += p0.y; acc[1] += p1.x; acc[2] += p1.y; acc[3] += p2.x;
            acc[4] += p2.y; acc[5] += p3.x; acc[6] += p3.y; acc[7] += p4.x;
            acc[8] += p4.y;

            acc[9]  += l0.y; acc[10] += l1.x; acc[11] += l1.y; acc[12] += l2.x;
            acc[13] += l2.y; acc[14] += l3.x; acc[15] += l3.y; acc[16] += l4.x;
            acc[17] += l4.y;

            const float p0v = p0.x, y0v = l0.x;
            acc[18] += y0v;
            acc[19] += -(y0v * __logf(p0v) + (1.0f - y0v) * __logf(1.0f - p0v));
        }
        __syncthreads();   // buffer buf is rewritten by prefetch(c + DEPTH)
    }

    asm volatile("cp.async.wait_group 0;");      // drain dummy groups

    // ---- warp + block reduce the 20 accumulators ----
#pragma unroll
    for (int i = 0; i < NACC; i++) {
#pragma unroll
        for (int off = 16; off > 0; off >>= 1)
            acc[i] += __shfl_xor_sync(0xFFFFFFFFu, acc[i], off);
    }

    __shared__ float s_red[NWARP * NACC];
    const int wid  = tid >> 5;
    const int lane = tid & 31;
    if (lane == 0) {
#pragma unroll
        for (int i = 0; i < NACC; i++) s_red[wid * NACC + i] = acc[i];
    }
    __syncthreads();

    if (tid < NACC) {
        float s = 0.0f;
#pragma unroll
        for (int w = 0; w < NWARP; w++) s += s_red[w * NACC + tid];
        g_partials[tid * NBLK + b * SLOTS + slot] = s;   // accumulator-major
    }

    // ---- ticket: last finished block finalizes ----
    __shared__ int s_last;
    __threadfence();
    __syncthreads();
    if (tid == 0) {
        unsigned int t = atomicAdd(&g_ticket, 1u);
        s_last = (t == (unsigned int)(NBLK - 1)) ? 1 : 0;
    }
    __syncthreads();
    if (!s_last) return;

    if (tid == 0) g_ticket = 0;
    __threadfence();

    // ---- Phase 2: thread b (<128) finalizes batch b; L2-hot coalesced float4 ----
    float num = 0.0f, wsum = 0.0f;
    if (tid < BATCH) {
        const float4* gp = (const float4*)g_partials;
        float a[NACC];
#pragma unroll
        for (int i = 0; i < NACC; i++) {
            float4 x = gp[i * (NBLK / 4) + tid * 2];
            float4 y = gp[i * (NBLK / 4) + tid * 2 + 1];
            a[i] = ((x.x + x.y) + (x.z + x.w)) + ((y.x + y.y) + (y.z + y.w));
        }

        const float len = (float)__ldg(&seq_lens[tid]);
        const float inv = 1.0f / len;

        float exam = 0.0f;
#pragma unroll
        for (int c = 0; c < 9; c++) {
            const float pm = a[c]     * inv;
            const float ym = a[9 + c] * inv;
            exam += c_w[c] * (-(ym * __logf(pm) + (1.0f - ym) * __logf(1.0f - pm)));
        }

        const float y0m = a[18] * inv;
        const float iw  = IMAGE_WEIGHT * y0m;
        num  = exam + a[19] * iw;
        wsum = iw * len;
    }

#pragma unroll
    for (int off = 16; off > 0; off >>= 1) {
        num  += __shfl_xor_sync(0xFFFFFFFFu, num,  off);
        wsum += __shfl_xor_sync(0xFFFFFFFFu, wsum, off);
    }
    __shared__ float s_num[NWARP], s_ws[NWARP];
    if (lane == 0) { s_num[wid] = num; s_ws[wid] = wsum; }
    __syncthreads();
    if (tid == 0) {
        float n = 0.0f, w = 0.0f;
#pragma unroll
        for (int i = 0; i < NWARP; i++) { n += s_num[i]; w += s_ws[i]; }
        float sumw = 0.0f;
#pragma unroll
        for (int c = 0; c < 9; c++) sumw += c_w[c];
        out[0] = n / ((float)BATCH * sumw + w);
    }
}

extern "C" void kernel_launch(void* const* d_in, const int* in_sizes, int n_in,
                              void* d_out, int out_size)
{
    const float* pred  = (const float*)d_in[0];
    const float* label = (const float*)d_in[1];
    const int*   slens = (const int*)d_in[2];
    float* out = (float*)d_out;

    dim3 grid(SLOTS, BATCH);
    rsna_fused_kernel<<<grid, NT>>>(pred, label, slens, out);
}